// round 11
// baseline (speedup 1.0000x reference)
#include <cuda_runtime.h>
#include <cstdint>

// x: (B=2, C=16, D=16, H=256, W=256) fp32
// out: (B=2, 4*C=64, D=16, 128, 128) fp32, subbands LL/HL/LH/HH at channel groups 0..3
//
// Per 2x2 block: x1=x[2i,2j]/2, x2=x[2i+1,2j]/2, x3=x[2i,2j+1]/2, x4=x[2i+1,2j+1]/2
// Butterfly: a=x1+x2, b=x3+x4, c=x2-x1, d=x4-x3
//   LL=a+b ; HL=b-a ; LH=c+d ; HH=d-c

struct f8 { float v[8]; };

// 256-bit load, L2 evict_last.
__device__ __forceinline__ f8 ldg256_evict_last(const float* p) {
    unsigned r0, r1, r2, r3, r4, r5, r6, r7;
    asm volatile(
        "ld.global.nc.L2::evict_last.v8.b32 {%0,%1,%2,%3,%4,%5,%6,%7}, [%8];"
        : "=r"(r0), "=r"(r1), "=r"(r2), "=r"(r3),
          "=r"(r4), "=r"(r5), "=r"(r6), "=r"(r7)
        : "l"(p));
    f8 o;
    o.v[0] = __uint_as_float(r0); o.v[1] = __uint_as_float(r1);
    o.v[2] = __uint_as_float(r2); o.v[3] = __uint_as_float(r3);
    o.v[4] = __uint_as_float(r4); o.v[5] = __uint_as_float(r5);
    o.v[6] = __uint_as_float(r6); o.v[7] = __uint_as_float(r7);
    return o;
}

__device__ __forceinline__ uint32_t smem_u32(const void* p) {
    uint32_t a;
    asm("{ .reg .u64 t; cvta.to.shared.u64 t, %1; cvt.u32.u64 %0, t; }"
        : "=r"(a) : "l"(p));
    return a;
}

// CTA: one plane x 8 output rows x 128 cols. Outputs staged in smem, written
// as four 4KB cp.async.bulk shared->global stores (one fully-contiguous burst
// per subband stream).
__global__ __launch_bounds__(256, 8)
void dwt_haar_kernel(const float* __restrict__ x, float* __restrict__ out) {
    __shared__ float4 sbuf[4][256];   // [stream][il*32 + j4], 16KB

    const unsigned t  = threadIdx.x;
    const unsigned j4 = t & 31u;          // 0..31 (output col / 4)
    const unsigned il = t >> 5;           // 0..7  (output row within CTA)
    const unsigned plane = blockIdx.x >> 4;          // 0..511
    const unsigned i     = ((blockIdx.x & 15u) << 3) | il;  // 0..127

    // ---- input: rows 2i, 2i+1, cols [8*j4, 8*j4+8) — 2 front-batched LDG.256
    const unsigned ioff = (plane << 16) + (i << 9) + (j4 << 3);
    const f8 r0 = ldg256_evict_last(x + ioff);
    const f8 r1 = ldg256_evict_last(x + ioff + 256u);

    float4 res[4];   // LL, HL, LH, HH
#pragma unroll
    for (int k = 0; k < 4; k++) {
        const float x1 = r0.v[2 * k]     * 0.5f;
        const float x3 = r0.v[2 * k + 1] * 0.5f;
        const float x2 = r1.v[2 * k]     * 0.5f;
        const float x4 = r1.v[2 * k + 1] * 0.5f;
        const float a = x1 + x2, b = x3 + x4;
        const float c = x2 - x1, d = x4 - x3;
        reinterpret_cast<float*>(&res[0])[k] = a + b;   // LL
        reinterpret_cast<float*>(&res[1])[k] = b - a;   // HL
        reinterpret_cast<float*>(&res[2])[k] = c + d;   // LH
        reinterpret_cast<float*>(&res[3])[k] = d - c;   // HH
    }

#pragma unroll
    for (int s = 0; s < 4; s++) sbuf[s][(il << 5) | j4] = res[s];

    __syncthreads();
    asm volatile("fence.proxy.async.shared::cta;" ::: "memory");

    if (t == 0) {
        // output base: plane (b*64*16 + c*16 + d), rows [i0, i0+8), all cols
        const unsigned oplane = ((plane >> 8) << 10) | (plane & 255u);
        const unsigned obase  = oplane * 16384u + ((blockIdx.x & 15u) << 10); // i0*128
        const unsigned gstride = 16u * 16u * 16384u;   // floats per subband group
#pragma unroll
        for (int s = 0; s < 4; s++) {
            const float* dst = out + obase + (unsigned)s * gstride;
            const uint32_t src = smem_u32(&sbuf[s][0]);
            asm volatile(
                "cp.async.bulk.global.shared::cta.bulk_group [%0], [%1], %2;"
                :: "l"(dst), "r"(src), "n"(4096) : "memory");
        }
        asm volatile("cp.async.bulk.commit_group;" ::: "memory");
        asm volatile("cp.async.bulk.wait_group 0;" ::: "memory");
    }
}

extern "C" void kernel_launch(void* const* d_in, const int* in_sizes, int n_in,
                              void* d_out, int out_size) {
    const float* x = (const float*)d_in[0];
    float* out = (float*)d_out;
    const int grid = 512 * 16;   // 8192 CTAs: plane x row-octet
    dwt_haar_kernel<<<grid, 256>>>(x, out);
}